// round 1
// baseline (speedup 1.0000x reference)
#include <cuda_runtime.h>

#define NN   100000
#define EE   3200000
#define GG   64
#define INC  128
#define HIDC 16
#define OUTC 8
#define EDGC 16

// ---------------- scratch (device globals: no allocation allowed) ----------------
__device__ int   g_src[EE];
__device__ int   g_dst[EE];
__device__ float g_norm[EE];
__device__ int   g_deg[NN];
__device__ float g_dinv[NN];
__device__ float g_A[NN * HIDC];      // sum_e norm_e * edge_attr_e  at dst
__device__ float g_emb1[NN * HIDC];
__device__ float g_agg1[NN * HIDC];
__device__ float g_emb2[NN * HIDC];
__device__ float g_agg2[NN * HIDC];
__device__ float g_pool[GG * HIDC];
__device__ int   g_cnt[GG];
__device__ int   g_w64;               // 1 if indices are int64, 0 if int32

// vector reduction (sm_90+): 4 floats, one L2 RMW op
__device__ __forceinline__ void red_add_v4(float* p, float4 v) {
    asm volatile("red.global.add.v4.f32 [%0], {%1,%2,%3,%4};"
                 :: "l"(p), "f"(v.x), "f"(v.y), "f"(v.z), "f"(v.w)
                 : "memory");
}

// ---------------- kernels ----------------

// Detect index dtype: int64 little-endian high words of node ids (< 2^31) are 0.
__global__ void k_detect(const unsigned* __restrict__ ei) {
    if (threadIdx.x == 0 && blockIdx.x == 0) {
        int ok = 1;
#pragma unroll
        for (int k = 0; k < 8; k++)
            if (ei[2 * k + 1] != 0u) ok = 0;
        g_w64 = ok;
    }
}

__global__ void k_init(int n_nodes) {
    int t = blockIdx.x * blockDim.x + threadIdx.x;
    if (t < n_nodes)          g_deg[t] = 0;
    if (t < n_nodes * HIDC)   g_A[t] = 0.f;
    if (t < GG * HIDC)        g_pool[t] = 0.f;
    if (t < GG)               g_cnt[t] = 0;
}

// Convert edge_index to int32 scratch + degree histogram (dst includes self-loop later via +1)
__global__ void k_deg(const void* __restrict__ ei, int E) {
    int e = blockIdx.x * blockDim.x + threadIdx.x;
    if (e >= E) return;
    int s, d;
    if (g_w64) {
        const long long* p = (const long long*)ei;
        s = (int)p[e]; d = (int)p[E + e];
    } else {
        const int* p = (const int*)ei;
        s = p[e]; d = p[E + e];
    }
    g_src[e] = s;
    g_dst[e] = d;
    atomicAdd(&g_deg[d], 1);
}

__global__ void k_dinv(int n_nodes) {
    int n = blockIdx.x * blockDim.x + threadIdx.x;
    if (n >= n_nodes) return;
    // self-loop adds 1 to every degree -> always > 0
    g_dinv[n] = rsqrtf((float)(g_deg[n] + 1));
}

// One pass over edge_attr: cache norm[e], aggregate A[dst] += norm * edge_attr
// 4 threads per edge, each owning 4 channels (float4).
__global__ void k_passB(const float4* __restrict__ ea4, int E) {
    int t = blockIdx.x * blockDim.x + threadIdx.x;
    if (t >= 4 * E) return;
    int e = t >> 2, q = t & 3;
    int s = g_src[e], d = g_dst[e];
    float nm = g_dinv[s] * g_dinv[d];
    if (q == 0) g_norm[e] = nm;
    float4 v = ea4[t];                 // t == e*4 + q
    v.x *= nm; v.y *= nm; v.z *= nm; v.w *= nm;
    red_add_v4(&g_A[d * HIDC + q * 4], v);
}

// Layer-1: emb1 = x @ W1_node ; agg1 = A @ W1_edge + dinv^2 * emb1 (self-loop term)
__global__ void k_emb1(const float* __restrict__ x,
                       const float* __restrict__ Wn,
                       const float* __restrict__ We,
                       int n_nodes) {
    __shared__ float sWn[INC * HIDC];
    __shared__ float sWe[HIDC * HIDC];
    int tid = threadIdx.x;
    for (int i = tid; i < INC * HIDC; i += blockDim.x) sWn[i] = Wn[i];
    if (tid < HIDC * HIDC) sWe[tid] = We[tid];
    __syncthreads();
    int t = blockIdx.x * blockDim.x + tid;
    if (t >= n_nodes * HIDC) return;
    int n = t >> 4, c = t & 15;
    const float4* x4 = (const float4*)(x + (size_t)n * INC);
    float acc = 0.f;
#pragma unroll
    for (int j = 0; j < INC / 4; j++) {
        float4 v = x4[j];
        acc = fmaf(v.x, sWn[(4 * j + 0) * HIDC + c], acc);
        acc = fmaf(v.y, sWn[(4 * j + 1) * HIDC + c], acc);
        acc = fmaf(v.z, sWn[(4 * j + 2) * HIDC + c], acc);
        acc = fmaf(v.w, sWn[(4 * j + 3) * HIDC + c], acc);
    }
    const float4* a4 = (const float4*)(g_A + n * HIDC);
    float ae = 0.f;
#pragma unroll
    for (int j = 0; j < HIDC / 4; j++) {
        float4 v = a4[j];
        ae = fmaf(v.x, sWe[(4 * j + 0) * HIDC + c], ae);
        ae = fmaf(v.y, sWe[(4 * j + 1) * HIDC + c], ae);
        ae = fmaf(v.z, sWe[(4 * j + 2) * HIDC + c], ae);
        ae = fmaf(v.w, sWe[(4 * j + 3) * HIDC + c], ae);
    }
    float di = g_dinv[n];
    g_emb1[t] = acc;
    g_agg1[t] = ae + di * di * acc;
}

// Edge gather/scatter pass (shared by both layers): agg[dst] += norm * emb[src]
__global__ void k_edge(int layer, int E) {
    int t = blockIdx.x * blockDim.x + threadIdx.x;
    if (t >= 4 * E) return;
    int e = t >> 2, q = t & 3;
    int s = g_src[e], d = g_dst[e];
    float nm = g_norm[e];
    const float4* emb = (const float4*)(layer == 1 ? g_emb1 : g_emb2);
    float* agg = (layer == 1 ? g_agg1 : g_agg2);
    float4 v = emb[s * 4 + q];
    v.x *= nm; v.y *= nm; v.z *= nm; v.w *= nm;
    red_add_v4(&agg[d * HIDC + q * 4], v);
}

// Layer-2: emb2 = relu(agg1) @ W2_node ; agg2 = A @ W2_edge + dinv^2 * emb2
__global__ void k_emb2(const float* __restrict__ Wn,
                       const float* __restrict__ We,
                       int n_nodes) {
    __shared__ float sWn[HIDC * HIDC];
    __shared__ float sWe[HIDC * HIDC];
    int tid = threadIdx.x;
    if (tid < HIDC * HIDC) { sWn[tid] = Wn[tid]; sWe[tid] = We[tid]; }
    __syncthreads();
    int t = blockIdx.x * blockDim.x + tid;
    if (t >= n_nodes * HIDC) return;
    int n = t >> 4, c = t & 15;
    const float* h = g_agg1 + n * HIDC;
    float acc = 0.f;
#pragma unroll
    for (int k = 0; k < HIDC; k++)
        acc = fmaf(fmaxf(h[k], 0.f), sWn[k * HIDC + c], acc);
    const float4* a4 = (const float4*)(g_A + n * HIDC);
    float ae = 0.f;
#pragma unroll
    for (int j = 0; j < HIDC / 4; j++) {
        float4 v = a4[j];
        ae = fmaf(v.x, sWe[(4 * j + 0) * HIDC + c], ae);
        ae = fmaf(v.y, sWe[(4 * j + 1) * HIDC + c], ae);
        ae = fmaf(v.z, sWe[(4 * j + 2) * HIDC + c], ae);
        ae = fmaf(v.w, sWe[(4 * j + 3) * HIDC + c], ae);
    }
    float di = g_dinv[n];
    g_emb2[t] = acc;
    g_agg2[t] = ae + di * di * acc;
}

// Mean-pool relu(agg2) by (sorted) batch index, via smem partials per block
__global__ void k_pool(const void* __restrict__ batch, int n_nodes) {
    __shared__ float sacc[GG * HIDC];
    __shared__ int scnt[GG];
    int tid = threadIdx.x;
    for (int i = tid; i < GG * HIDC; i += blockDim.x) sacc[i] = 0.f;
    if (tid < GG) scnt[tid] = 0;
    __syncthreads();
    int n = blockIdx.x * blockDim.x + tid;
    if (n < n_nodes) {
        int g = g_w64 ? (int)((const long long*)batch)[n]
                      : ((const int*)batch)[n];
        atomicAdd(&scnt[g], 1);
#pragma unroll
        for (int c = 0; c < HIDC; c++)
            atomicAdd(&sacc[g * HIDC + c], fmaxf(g_agg2[n * HIDC + c], 0.f));
    }
    __syncthreads();
    for (int i = tid; i < GG * HIDC; i += blockDim.x)
        if (sacc[i] != 0.f) atomicAdd(&g_pool[i], sacc[i]);
    if (tid < GG && scnt[tid] > 0) atomicAdd(&g_cnt[tid], scnt[tid]);
}

// out[g,o] = (pool[g]/max(cnt,1)) @ node_W + b
__global__ void k_final(const float* __restrict__ W,
                        const float* __restrict__ b,
                        float* __restrict__ out) {
    int t = threadIdx.x;
    if (t >= GG * OUTC) return;
    int g = t / OUTC, o = t % OUTC;
    float inv = 1.f / fmaxf((float)g_cnt[g], 1.f);
    float s = b[o];
#pragma unroll
    for (int k = 0; k < HIDC; k++)
        s = fmaf(g_pool[g * HIDC + k] * inv, W[k * OUTC + o], s);
    out[t] = s;
}

// ---------------- launch ----------------
extern "C" void kernel_launch(void* const* d_in, const int* in_sizes, int n_in,
                              void* d_out, int out_size) {
    const float* x    = (const float*)d_in[0];
    const void*  ei   = d_in[1];
    const float* ea   = (const float*)d_in[2];
    const void*  bidx = d_in[3];
    const float* W1n  = (const float*)d_in[4];
    const float* W1e  = (const float*)d_in[5];
    const float* W2n  = (const float*)d_in[6];
    const float* W2e  = (const float*)d_in[7];
    const float* nW   = (const float*)d_in[8];
    const float* nb   = (const float*)d_in[9];
    float* out = (float*)d_out;

    int N = in_sizes[0] / INC;        // nodes
    int E = in_sizes[2] / EDGC;       // edges
    if (N > NN) N = NN;
    if (E > EE) E = EE;

    const int B = 256;
    k_detect<<<1, 32>>>((const unsigned*)ei);
    k_init<<<(N * HIDC + B - 1) / B, B>>>(N);
    k_deg<<<(E + B - 1) / B, B>>>(ei, E);
    k_dinv<<<(N + B - 1) / B, B>>>(N);
    k_passB<<<(4 * E + B - 1) / B, B>>>((const float4*)ea, E);
    k_emb1<<<(N * HIDC + B - 1) / B, B>>>(x, W1n, W1e, N);
    k_edge<<<(4 * E + B - 1) / B, B>>>(1, E);
    k_emb2<<<(N * HIDC + B - 1) / B, B>>>(W2n, W2e, N);
    k_edge<<<(4 * E + B - 1) / B, B>>>(2, E);
    k_pool<<<(N + B - 1) / B, B>>>(bidx, N);
    k_final<<<1, GG * OUTC>>>(nW, nb, out);
}